// round 2
// baseline (speedup 1.0000x reference)
#include <cuda_runtime.h>
#include <math.h>

#define NUM_LEVELS 16
#define TABLE_SIZE (1u << 19)
#define TMASK (TABLE_SIZE - 1u)
#define PRIME1 2654435761u
#define PRIME2 805459861u

struct LevelParams {
    float scale[NUM_LEVELS];
    unsigned res[NUM_LEVELS];
    unsigned dense[NUM_LEVELS];
};

__global__ __launch_bounds__(256)
void hashgrid_mlp_kernel(const float* __restrict__ points,
                         const float2* __restrict__ tables,
                         const float* __restrict__ gW1,
                         const float* __restrict__ gW2,
                         const float* __restrict__ gW3,
                         const float* __restrict__ aabb,
                         float* __restrict__ out,
                         int n, LevelParams lp)
{
    __shared__ __align__(16) float sW1[1024];
    __shared__ __align__(16) float sW2[1024];
    __shared__ __align__(16) float sW3[128];

    for (int i = threadIdx.x; i < 1024; i += 256) {
        sW1[i] = gW1[i];
        sW2[i] = gW2[i];
    }
    if (threadIdx.x < 128) sW3[threadIdx.x] = gW3[threadIdx.x];
    __syncthreads();

    int tid = blockIdx.x * 256 + threadIdx.x;
    if (tid >= n) return;

    float lox = aabb[0], loy = aabb[1], loz = aabb[2];
    float hix = aabb[3], hiy = aabb[4], hiz = aabb[5];
    float px = points[tid * 3 + 0];
    float py = points[tid * 3 + 1];
    float pz = points[tid * 3 + 2];

    float tx = fminf(fmaxf((px - lox) / (hix - lox), 0.f), 1.f);
    float ty = fminf(fmaxf((py - loy) / (hiy - loy), 0.f), 1.f);
    float tz = fminf(fmaxf((pz - loz) / (hiz - loz), 0.f), 1.f);

    float h1[32];
#pragma unroll
    for (int o = 0; o < 32; ++o) h1[o] = 0.f;

#pragma unroll 1
    for (int l = 0; l < NUM_LEVELS; ++l) {
        const float s = lp.scale[l];
        const unsigned res = lp.res[l];
        const unsigned rm1 = res - 1u;

        float posx = tx * s + 0.5f;
        float posy = ty * s + 0.5f;
        float posz = tz * s + 0.5f;
        float fx = floorf(posx), fy = floorf(posy), fz = floorf(posz);
        float wx = posx - fx, wy = posy - fy, wz = posz - fz;

        unsigned bx = (unsigned)fx, by = (unsigned)fy, bz = (unsigned)fz;
        unsigned x0 = min(bx, rm1),      x1 = min(bx + 1u, rm1);
        unsigned y0 = min(by, rm1),      y1 = min(by + 1u, rm1);
        unsigned z0 = min(bz, rm1),      z1 = min(bz + 1u, rm1);

        unsigned i000, i100, i010, i110, i001, i101, i011, i111;
        if (lp.dense[l]) {
            unsigned r2 = res * res;
            unsigned a0 = y0 * res, a1 = y1 * res;
            unsigned b0 = z0 * r2,  b1 = z1 * r2;
            i000 = x0 + a0 + b0;  i100 = x1 + a0 + b0;
            i010 = x0 + a1 + b0;  i110 = x1 + a1 + b0;
            i001 = x0 + a0 + b1;  i101 = x1 + a0 + b1;
            i011 = x0 + a1 + b1;  i111 = x1 + a1 + b1;
        } else {
            unsigned a0 = y0 * PRIME1, a1 = y1 * PRIME1;
            unsigned b0 = z0 * PRIME2, b1 = z1 * PRIME2;
            i000 = (x0 ^ a0 ^ b0) & TMASK;  i100 = (x1 ^ a0 ^ b0) & TMASK;
            i010 = (x0 ^ a1 ^ b0) & TMASK;  i110 = (x1 ^ a1 ^ b0) & TMASK;
            i001 = (x0 ^ a0 ^ b1) & TMASK;  i101 = (x1 ^ a0 ^ b1) & TMASK;
            i011 = (x0 ^ a1 ^ b1) & TMASK;  i111 = (x1 ^ a1 ^ b1) & TMASK;
        }

        const float2* t = tables + (size_t)l * TABLE_SIZE;
        float2 c000 = __ldg(t + i000);
        float2 c100 = __ldg(t + i100);
        float2 c010 = __ldg(t + i010);
        float2 c110 = __ldg(t + i110);
        float2 c001 = __ldg(t + i001);
        float2 c101 = __ldg(t + i101);
        float2 c011 = __ldg(t + i011);
        float2 c111 = __ldg(t + i111);

        float wx0 = 1.f - wx, wy0 = 1.f - wy, wz0 = 1.f - wz;
        float wyz00 = wy0 * wz0, wyz10 = wy * wz0;
        float wyz01 = wy0 * wz,  wyz11 = wy * wz;

        float g0a = wyz00 * c000.x + wyz10 * c010.x + wyz01 * c001.x + wyz11 * c011.x;
        float g0b = wyz00 * c100.x + wyz10 * c110.x + wyz01 * c101.x + wyz11 * c111.x;
        float f0 = wx0 * g0a + wx * g0b;
        float g1a = wyz00 * c000.y + wyz10 * c010.y + wyz01 * c001.y + wyz11 * c011.y;
        float g1b = wyz00 * c100.y + wyz10 * c110.y + wyz01 * c101.y + wyz11 * c111.y;
        float f1 = wx0 * g1a + wx * g1b;

        // Fused layer-1 accumulation: h1 += f0*W1[:,2l] + f1*W1[:,2l+1]
        const float2* wrow = (const float2*)(sW1 + 2 * l);
#pragma unroll
        for (int o = 0; o < 32; ++o) {
            float2 w = wrow[o * 16];
            h1[o] = fmaf(f0, w.x, fmaf(f1, w.y, h1[o]));
        }
    }

#pragma unroll
    for (int o = 0; o < 32; ++o) h1[o] = fmaxf(h1[o], 0.f);

    float h2[32];
#pragma unroll
    for (int o = 0; o < 32; ++o) {
        const float4* w = (const float4*)(sW2 + o * 32);
        float acc = 0.f;
#pragma unroll
        for (int i = 0; i < 8; ++i) {
            float4 q = w[i];
            acc += h1[4 * i + 0] * q.x + h1[4 * i + 1] * q.y
                 + h1[4 * i + 2] * q.z + h1[4 * i + 3] * q.w;
        }
        h2[o] = fmaxf(acc, 0.f);
    }

    float o4[4];
#pragma unroll
    for (int o = 0; o < 4; ++o) {
        const float4* w = (const float4*)(sW3 + o * 32);
        float acc = 0.f;
#pragma unroll
        for (int i = 0; i < 8; ++i) {
            float4 q = w[i];
            acc += h2[4 * i + 0] * q.x + h2[4 * i + 1] * q.y
                 + h2[4 * i + 2] * q.z + h2[4 * i + 3] * q.w;
        }
        o4[o] = acc;
    }

    float4 r;
    r.x = 1.f / (1.f + __expf(-o4[0]));
    r.y = 1.f / (1.f + __expf(-o4[1]));
    r.z = 1.f / (1.f + __expf(-o4[2]));
    float s3 = 1.f / (1.f + __expf(-o4[3]));
    r.w = s3 * 0.99f + 0.01f;

    ((float4*)out)[tid] = r;
}

extern "C" void kernel_launch(void* const* d_in, const int* in_sizes, int n_in,
                              void* d_out, int out_size)
{
    (void)n_in; (void)out_size;
    // Replicate the reference's level-constant computation exactly in double,
    // so the discrete decisions (ceil -> res, dense-vs-hash) match.
    LevelParams lp;
    const double b = exp(log(4096.0 / 16.0) / 15.0);
    for (int l = 0; l < NUM_LEVELS; ++l) {
        double sc = 16.0 * pow(b, (double)l) - 1.0;
        int res = (int)ceil(sc) + 1;
        lp.scale[l] = (float)sc;  // jax does fp32 math with the fp32-rounded scalar
        lp.res[l] = (unsigned)res;
        long long r3 = (long long)res * res * res;
        lp.dense[l] = (r3 <= (long long)TABLE_SIZE) ? 1u : 0u;
    }

    int n = in_sizes[0] / 3;
    dim3 grid((n + 255) / 256);
    hashgrid_mlp_kernel<<<grid, 256>>>(
        (const float*)d_in[0],
        (const float2*)d_in[1],
        (const float*)d_in[2],
        (const float*)d_in[3],
        (const float*)d_in[4],
        (const float*)d_in[5],
        (float*)d_out, n, lp);
}

// round 3
// speedup vs baseline: 1.0187x; 1.0187x over previous
#include <cuda_runtime.h>
#include <math.h>

#define NUM_LEVELS 16
#define TABLE_SIZE (1u << 19)
#define TMASK (TABLE_SIZE - 1u)
#define PRIME1 2654435761u
#define PRIME2 805459861u

struct LevelParams {
    float scale[NUM_LEVELS];
    unsigned res[NUM_LEVELS];
    unsigned dense[NUM_LEVELS];
};

// Weights in constant memory: reads go through the uniform-const port (LDCU),
// NOT l1tex — removes ~20% of the saturated l1tex wavefront traffic.
__constant__ float cW1[1024];   // [32 out][32 in] row-major (W1[o][i])
__constant__ float cW2[1024];
__constant__ float cW3[128];

__global__ __launch_bounds__(256)
void hashgrid_mlp_kernel(const float* __restrict__ points,
                         const float2* __restrict__ tables,
                         const float* __restrict__ aabb,
                         float* __restrict__ out,
                         int n, LevelParams lp)
{
    int tid = blockIdx.x * 256 + threadIdx.x;
    if (tid >= n) return;

    float lox = aabb[0], loy = aabb[1], loz = aabb[2];
    float hix = aabb[3], hiy = aabb[4], hiz = aabb[5];
    float px = points[tid * 3 + 0];
    float py = points[tid * 3 + 1];
    float pz = points[tid * 3 + 2];

    float tx = fminf(fmaxf((px - lox) / (hix - lox), 0.f), 1.f);
    float ty = fminf(fmaxf((py - loy) / (hiy - loy), 0.f), 1.f);
    float tz = fminf(fmaxf((pz - loz) / (hiz - loz), 0.f), 1.f);

    float h1[32];
#pragma unroll
    for (int o = 0; o < 32; ++o) h1[o] = 0.f;

#pragma unroll 1
    for (int l = 0; l < NUM_LEVELS; ++l) {
        const float s = lp.scale[l];
        const unsigned res = lp.res[l];
        const unsigned rm1 = res - 1u;

        float posx = tx * s + 0.5f;
        float posy = ty * s + 0.5f;
        float posz = tz * s + 0.5f;
        float fx = floorf(posx), fy = floorf(posy), fz = floorf(posz);
        float wx = posx - fx, wy = posy - fy, wz = posz - fz;

        unsigned bx = (unsigned)fx, by = (unsigned)fy, bz = (unsigned)fz;
        unsigned x0 = min(bx, rm1),      x1 = min(bx + 1u, rm1);
        unsigned y0 = min(by, rm1),      y1 = min(by + 1u, rm1);
        unsigned z0 = min(bz, rm1),      z1 = min(bz + 1u, rm1);

        unsigned i000, i100, i010, i110, i001, i101, i011, i111;
        if (lp.dense[l]) {
            unsigned r2 = res * res;
            unsigned a0 = y0 * res, a1 = y1 * res;
            unsigned b0 = z0 * r2,  b1 = z1 * r2;
            i000 = x0 + a0 + b0;  i100 = x1 + a0 + b0;
            i010 = x0 + a1 + b0;  i110 = x1 + a1 + b0;
            i001 = x0 + a0 + b1;  i101 = x1 + a0 + b1;
            i011 = x0 + a1 + b1;  i111 = x1 + a1 + b1;
        } else {
            unsigned a0 = y0 * PRIME1, a1 = y1 * PRIME1;
            unsigned b0 = z0 * PRIME2, b1 = z1 * PRIME2;
            i000 = (x0 ^ a0 ^ b0) & TMASK;  i100 = (x1 ^ a0 ^ b0) & TMASK;
            i010 = (x0 ^ a1 ^ b0) & TMASK;  i110 = (x1 ^ a1 ^ b0) & TMASK;
            i001 = (x0 ^ a0 ^ b1) & TMASK;  i101 = (x1 ^ a0 ^ b1) & TMASK;
            i011 = (x0 ^ a1 ^ b1) & TMASK;  i111 = (x1 ^ a1 ^ b1) & TMASK;
        }

        const float2* t = tables + (size_t)l * TABLE_SIZE;
        float2 c000 = __ldg(t + i000);
        float2 c100 = __ldg(t + i100);
        float2 c010 = __ldg(t + i010);
        float2 c110 = __ldg(t + i110);
        float2 c001 = __ldg(t + i001);
        float2 c101 = __ldg(t + i101);
        float2 c011 = __ldg(t + i011);
        float2 c111 = __ldg(t + i111);

        float wx0 = 1.f - wx, wy0 = 1.f - wy, wz0 = 1.f - wz;
        float wyz00 = wy0 * wz0, wyz10 = wy * wz0;
        float wyz01 = wy0 * wz,  wyz11 = wy * wz;

        float g0a = wyz00 * c000.x + wyz10 * c010.x + wyz01 * c001.x + wyz11 * c011.x;
        float g0b = wyz00 * c100.x + wyz10 * c110.x + wyz01 * c101.x + wyz11 * c111.x;
        float f0 = wx0 * g0a + wx * g0b;
        float g1a = wyz00 * c000.y + wyz10 * c010.y + wyz01 * c001.y + wyz11 * c011.y;
        float g1b = wyz00 * c100.y + wyz10 * c110.y + wyz01 * c101.y + wyz11 * c111.y;
        float f1 = wx0 * g1a + wx * g1b;

        // Fused layer-1 accumulation: h1 += f0*W1[:,2l] + f1*W1[:,2l+1]
        // Weight reads are warp-uniform constant loads (LDCU, uniform port).
        const int wbase = 2 * l;
#pragma unroll
        for (int o = 0; o < 32; ++o) {
            float w0 = cW1[o * 32 + wbase];
            float w1 = cW1[o * 32 + wbase + 1];
            h1[o] = fmaf(f0, w0, fmaf(f1, w1, h1[o]));
        }
    }

#pragma unroll
    for (int o = 0; o < 32; ++o) h1[o] = fmaxf(h1[o], 0.f);

    float h2[32];
#pragma unroll
    for (int o = 0; o < 32; ++o) {
        float acc = 0.f;
#pragma unroll
        for (int i = 0; i < 32; ++i) {
            acc = fmaf(h1[i], cW2[o * 32 + i], acc);
        }
        h2[o] = fmaxf(acc, 0.f);
    }

    float o4[4];
#pragma unroll
    for (int o = 0; o < 4; ++o) {
        float acc = 0.f;
#pragma unroll
        for (int i = 0; i < 32; ++i) {
            acc = fmaf(h2[i], cW3[o * 32 + i], acc);
        }
        o4[o] = acc;
    }

    float4 r;
    r.x = 1.f / (1.f + __expf(-o4[0]));
    r.y = 1.f / (1.f + __expf(-o4[1]));
    r.z = 1.f / (1.f + __expf(-o4[2]));
    float s3 = 1.f / (1.f + __expf(-o4[3]));
    r.w = s3 * 0.99f + 0.01f;

    ((float4*)out)[tid] = r;
}

extern "C" void kernel_launch(void* const* d_in, const int* in_sizes, int n_in,
                              void* d_out, int out_size)
{
    (void)n_in; (void)out_size;
    LevelParams lp;
    const double b = exp(log(4096.0 / 16.0) / 15.0);
    for (int l = 0; l < NUM_LEVELS; ++l) {
        double sc = 16.0 * pow(b, (double)l) - 1.0;
        int res = (int)ceil(sc) + 1;
        lp.scale[l] = (float)sc;
        lp.res[l] = (unsigned)res;
        long long r3 = (long long)res * res * res;
        lp.dense[l] = (r3 <= (long long)TABLE_SIZE) ? 1u : 0u;
    }

    // Stage weights into constant memory (D2D async copy: graph-capturable,
    // no allocation). Reads then use the const port instead of l1tex.
    cudaMemcpyToSymbolAsync(cW1, d_in[2], 1024 * sizeof(float), 0,
                            cudaMemcpyDeviceToDevice, 0);
    cudaMemcpyToSymbolAsync(cW2, d_in[3], 1024 * sizeof(float), 0,
                            cudaMemcpyDeviceToDevice, 0);
    cudaMemcpyToSymbolAsync(cW3, d_in[4], 128 * sizeof(float), 0,
                            cudaMemcpyDeviceToDevice, 0);

    int n = in_sizes[0] / 3;
    dim3 grid((n + 255) / 256);
    hashgrid_mlp_kernel<<<grid, 256>>>(
        (const float*)d_in[0],
        (const float2*)d_in[1],
        (const float*)d_in[5],
        (float*)d_out, n, lp);
}

// round 4
// speedup vs baseline: 1.0357x; 1.0167x over previous
#include <cuda_runtime.h>
#include <math.h>

#define NUM_LEVELS 16
#define TABLE_SIZE (1u << 19)
#define TMASK (TABLE_SIZE - 1u)
#define PRIME1 2654435761u
#define PRIME2 805459861u

struct LevelParams {
    float scale[NUM_LEVELS];
    unsigned res[NUM_LEVELS];
    unsigned dense[NUM_LEVELS];
};

// Transposed weights in constant memory (uniform-const port, off l1tex).
// cW1T[i*32+o] = W1[o][i]; cW2T[i*32+o] = W2[o][i]; cW3T[i*4+o] = W3[o][i].
__constant__ float cW1T[1024];
__constant__ float cW2T[1024];
__constant__ float cW3T[128];

// Scratch for the transpose prep (no cudaMalloc allowed).
__device__ float g_scratch[2176];

typedef unsigned long long u64;

__device__ __forceinline__ u64 pack2(float a, float b) {
    u64 r; asm("mov.b64 %0, {%1,%2};" : "=l"(r) : "f"(a), "f"(b)); return r;
}
__device__ __forceinline__ void unpack2(u64 v, float& a, float& b) {
    asm("mov.b64 {%0,%1}, %2;" : "=f"(a), "=f"(b) : "l"(v));
}
__device__ __forceinline__ u64 fma2(u64 a, u64 b, u64 c) {
    u64 d; asm("fma.rn.f32x2 %0, %1, %2, %3;" : "=l"(d) : "l"(a), "l"(b), "l"(c));
    return d;
}
__device__ __forceinline__ u64 mul2(u64 a, u64 b) {
    u64 d; asm("mul.rn.f32x2 %0, %1, %2;" : "=l"(d) : "l"(a), "l"(b));
    return d;
}

__global__ void prep_transpose(const float* __restrict__ W1,
                               const float* __restrict__ W2,
                               const float* __restrict__ W3)
{
    int t = threadIdx.x;             // 1024 threads
    int o = t & 31, i = t >> 5;      // t = i*32 + o  (dest layout [i][o])
    g_scratch[t]        = W1[o * 32 + i];
    g_scratch[1024 + t] = W2[o * 32 + i];
    if (t < 128) {
        int o3 = t & 3, i3 = t >> 2; // dest [i][o], 4 outputs
        g_scratch[2048 + t] = W3[o3 * 32 + i3];
    }
}

__global__ __launch_bounds__(256, 4)
void hashgrid_mlp_kernel(const float* __restrict__ points,
                         const u64* __restrict__ tables,   // float2 as u64
                         const float* __restrict__ aabb,
                         float* __restrict__ out,
                         int n, LevelParams lp)
{
    int tid = blockIdx.x * 256 + threadIdx.x;
    if (tid >= n) return;

    float lox = aabb[0], loy = aabb[1], loz = aabb[2];
    float hix = aabb[3], hiy = aabb[4], hiz = aabb[5];
    float px = points[tid * 3 + 0];
    float py = points[tid * 3 + 1];
    float pz = points[tid * 3 + 2];

    float tx = fminf(fmaxf((px - lox) / (hix - lox), 0.f), 1.f);
    float ty = fminf(fmaxf((py - loy) / (hiy - loy), 0.f), 1.f);
    float tz = fminf(fmaxf((pz - loz) / (hiz - loz), 0.f), 1.f);

    // 16 packed accumulators = (h1[2j], h1[2j+1])
    u64 h1p[16];
    const u64 zz = 0ull;
#pragma unroll
    for (int j = 0; j < 16; ++j) h1p[j] = zz;

    const u64* cw1 = (const u64*)cW1T;

#pragma unroll 1
    for (int l = 0; l < NUM_LEVELS; ++l) {
        const float s = lp.scale[l];
        const unsigned res = lp.res[l];
        const unsigned rm1 = res - 1u;

        float posx = tx * s + 0.5f;
        float posy = ty * s + 0.5f;
        float posz = tz * s + 0.5f;
        float fx = floorf(posx), fy = floorf(posy), fz = floorf(posz);
        float wx = posx - fx, wy = posy - fy, wz = posz - fz;

        unsigned bx = (unsigned)fx, by = (unsigned)fy, bz = (unsigned)fz;
        unsigned x0 = min(bx, rm1),      x1 = min(bx + 1u, rm1);
        unsigned y0 = min(by, rm1),      y1 = min(by + 1u, rm1);
        unsigned z0 = min(bz, rm1),      z1 = min(bz + 1u, rm1);

        unsigned i000, i100, i010, i110, i001, i101, i011, i111;
        if (lp.dense[l]) {
            unsigned r2 = res * res;
            unsigned a0 = y0 * res, a1 = y1 * res;
            unsigned b0 = z0 * r2,  b1 = z1 * r2;
            i000 = x0 + a0 + b0;  i100 = x1 + a0 + b0;
            i010 = x0 + a1 + b0;  i110 = x1 + a1 + b0;
            i001 = x0 + a0 + b1;  i101 = x1 + a0 + b1;
            i011 = x0 + a1 + b1;  i111 = x1 + a1 + b1;
        } else {
            unsigned a0 = y0 * PRIME1, a1 = y1 * PRIME1;
            unsigned b0 = z0 * PRIME2, b1 = z1 * PRIME2;
            i000 = (x0 ^ a0 ^ b0) & TMASK;  i100 = (x1 ^ a0 ^ b0) & TMASK;
            i010 = (x0 ^ a1 ^ b0) & TMASK;  i110 = (x1 ^ a1 ^ b0) & TMASK;
            i001 = (x0 ^ a0 ^ b1) & TMASK;  i101 = (x1 ^ a0 ^ b1) & TMASK;
            i011 = (x0 ^ a1 ^ b1) & TMASK;  i111 = (x1 ^ a1 ^ b1) & TMASK;
        }

        const u64* t = tables + (size_t)l * TABLE_SIZE;
        u64 c000 = __ldg(t + i000);
        u64 c100 = __ldg(t + i100);
        u64 c010 = __ldg(t + i010);
        u64 c110 = __ldg(t + i110);
        u64 c001 = __ldg(t + i001);
        u64 c101 = __ldg(t + i101);
        u64 c011 = __ldg(t + i011);
        u64 c111 = __ldg(t + i111);

        float wx0 = 1.f - wx, wy0 = 1.f - wy, wz0 = 1.f - wz;
        u64 wyz00 = pack2(wy0 * wz0, wy0 * wz0);
        u64 wyz10 = pack2(wy * wz0,  wy * wz0);
        u64 wyz01 = pack2(wy0 * wz,  wy0 * wz);
        u64 wyz11 = pack2(wy * wz,   wy * wz);

        // Both feature channels interpolated together (f32x2).
        u64 ga = mul2(wyz00, c000);
        ga = fma2(wyz10, c010, ga);
        ga = fma2(wyz01, c001, ga);
        ga = fma2(wyz11, c011, ga);
        u64 gb = mul2(wyz00, c100);
        gb = fma2(wyz10, c110, gb);
        gb = fma2(wyz01, c101, gb);
        gb = fma2(wyz11, c111, gb);
        u64 fp = fma2(pack2(wx, wx), gb, mul2(pack2(wx0, wx0), ga));

        float f0, f1;
        unpack2(fp, f0, f1);
        u64 f0p = pack2(f0, f0);
        u64 f1p = pack2(f1, f1);

        // h1(pair j) += f0 * W1T[2l][2j..] + f1 * W1T[2l+1][2j..]
        const u64* w0 = cw1 + (2 * l) * 16;
        const u64* w1 = cw1 + (2 * l + 1) * 16;
#pragma unroll
        for (int j = 0; j < 16; ++j) {
            h1p[j] = fma2(f0p, w0[j], h1p[j]);
            h1p[j] = fma2(f1p, w1[j], h1p[j]);
        }
    }

    // relu + unpack h1
    float h1[32];
#pragma unroll
    for (int j = 0; j < 16; ++j) {
        float a, b;
        unpack2(h1p[j], a, b);
        h1[2 * j]     = fmaxf(a, 0.f);
        h1[2 * j + 1] = fmaxf(b, 0.f);
    }

    // Layer 2: packed over output pairs. h2p[j] = sum_i h1[i]*(W2T[i][2j],W2T[i][2j+1])
    const u64* cw2 = (const u64*)cW2T;
    u64 h2p[16];
#pragma unroll
    for (int j = 0; j < 16; ++j) h2p[j] = zz;
#pragma unroll
    for (int i = 0; i < 32; ++i) {
        u64 hb = pack2(h1[i], h1[i]);
        const u64* wr = cw2 + i * 16;
#pragma unroll
        for (int j = 0; j < 16; ++j) h2p[j] = fma2(hb, wr[j], h2p[j]);
    }

    float h2[32];
#pragma unroll
    for (int j = 0; j < 16; ++j) {
        float a, b;
        unpack2(h2p[j], a, b);
        h2[2 * j]     = fmaxf(a, 0.f);
        h2[2 * j + 1] = fmaxf(b, 0.f);
    }

    // Layer 3: 2 packed output pairs.
    const u64* cw3 = (const u64*)cW3T;
    u64 o01 = zz, o23 = zz;
#pragma unroll
    for (int i = 0; i < 32; ++i) {
        u64 hb = pack2(h2[i], h2[i]);
        o01 = fma2(hb, cw3[i * 2],     o01);
        o23 = fma2(hb, cw3[i * 2 + 1], o23);
    }
    float a0, a1, a2, a3;
    unpack2(o01, a0, a1);
    unpack2(o23, a2, a3);

    float4 r;
    r.x = 1.f / (1.f + __expf(-a0));
    r.y = 1.f / (1.f + __expf(-a1));
    r.z = 1.f / (1.f + __expf(-a2));
    float s3 = 1.f / (1.f + __expf(-a3));
    r.w = s3 * 0.99f + 0.01f;

    ((float4*)out)[tid] = r;
}

extern "C" void kernel_launch(void* const* d_in, const int* in_sizes, int n_in,
                              void* d_out, int out_size)
{
    (void)n_in; (void)out_size;
    LevelParams lp;
    const double b = exp(log(4096.0 / 16.0) / 15.0);
    for (int l = 0; l < NUM_LEVELS; ++l) {
        double sc = 16.0 * pow(b, (double)l) - 1.0;
        int res = (int)ceil(sc) + 1;
        lp.scale[l] = (float)sc;
        lp.res[l] = (unsigned)res;
        long long r3 = (long long)res * res * res;
        lp.dense[l] = (r3 <= (long long)TABLE_SIZE) ? 1u : 0u;
    }

    // Transpose weights on-device into scratch, then stage into constant mem.
    prep_transpose<<<1, 1024>>>((const float*)d_in[2],
                                (const float*)d_in[3],
                                (const float*)d_in[4]);
    void* scr = nullptr;
    cudaGetSymbolAddress(&scr, g_scratch);
    cudaMemcpyToSymbolAsync(cW1T, scr, 1024 * sizeof(float), 0,
                            cudaMemcpyDeviceToDevice, 0);
    cudaMemcpyToSymbolAsync(cW2T, (char*)scr + 1024 * sizeof(float),
                            1024 * sizeof(float), 0,
                            cudaMemcpyDeviceToDevice, 0);
    cudaMemcpyToSymbolAsync(cW3T, (char*)scr + 2048 * sizeof(float),
                            128 * sizeof(float), 0,
                            cudaMemcpyDeviceToDevice, 0);

    int n = in_sizes[0] / 3;
    dim3 grid((n + 255) / 256);
    hashgrid_mlp_kernel<<<grid, 256>>>(
        (const float*)d_in[0],
        (const u64*)d_in[1],
        (const float*)d_in[5],
        (float*)d_out, n, lp);
}